// round 9
// baseline (speedup 1.0000x reference)
#include <cuda_runtime.h>

// RWKV WKV single-pass warp-scan, v3.
//   a_t = d_t a_{t-1} + ek_t v_t ; b_t = d_t b_{t-1} + ek_t
//   out = sigmoid(r) * a/(b+eps),  d = exp(-exp(w)), ek = exp(k)
//
// vs v2: r removed from the smem transpose (sigmoid applied at store stage in
// output layout), operands staged pre-converted (d, ek*v, ek), single-buffered
// smem (33.8 KB) with register prefetch -> 3 CTAs/SM.

#define B_      8
#define T_      4096
#define C_      1024
#define CBLK    32
#define TTILE   64
#define NITER   (T_ / TTILE)      // 64
#define THREADS 256
#define SROW    66                // even stride + skew -> conflict-free
#define REGF    (CBLK * SROW)     // 2112 floats per region
#define SMEMB   (4 * REGF * 4)    // d, ekv, ek, so = 33792 B
#define WKV_EPS 1e-6f

// Skewed transpose address (validated conflict-free both directions in v2).
__device__ __forceinline__ int saddr(int ch, int t) {
    return ch * SROW + ((t + 4 * (ch >> 2)) & 63);
}

__device__ __forceinline__ void cvt(const float4 wv, const float4 kv, const float4 vv,
                                    float4& d4, float4& e4, float4& x4) {
    d4.x = __expf(-__expf(wv.x));  e4.x = __expf(kv.x);  x4.x = e4.x * vv.x;
    d4.y = __expf(-__expf(wv.y));  e4.y = __expf(kv.y);  x4.y = e4.y * vv.y;
    d4.z = __expf(-__expf(wv.z));  e4.z = __expf(kv.z);  x4.z = e4.z * vv.z;
    d4.w = __expf(-__expf(wv.w));  e4.w = __expf(kv.w);  x4.w = e4.w * vv.w;
}

__global__ void __launch_bounds__(THREADS, 3)
wkv_scan3(const float4* __restrict__ r, const float4* __restrict__ w,
          const float4* __restrict__ k, const float4* __restrict__ v,
          float4* __restrict__ out) {
    extern __shared__ float S[];
    float* sd  = S;                // decay d
    float* sev = S + REGF;         // ek*v
    float* se  = S + 2 * REGF;     // ek
    float* so  = S + 3 * REGF;     // output a/(b+eps)

    const int tid  = threadIdx.x;
    const int lane = tid & 31;
    const int wid  = tid >> 5;     // warp owns channels 4*wid..4*wid+3
    const int cl4  = tid & 7;      // float4 column (8 x 16B = 32 channels)
    const int tl   = tid >> 3;     // 0..31: t-rows tl and tl+32

    const int b  = blockIdx.x >> 5;
    const int c0 = (blockIdx.x & 31) * CBLK;
    const int rowF4 = C_ / 4;
    const int gco   = (b * T_) * rowF4 + (c0 >> 2) + cl4;

    // Prefetch + convert tile 0.
    float4 dd[2], ee[2], ev[2];
#pragma unroll
    for (int h = 0; h < 2; ++h) {
        const int g = gco + (tl + h * 32) * rowF4;
        cvt(__ldcs(&w[g]), __ldcs(&k[g]), __ldcs(&v[g]), dd[h], ee[h], ev[h]);
    }

    float aC[4] = {0.f, 0.f, 0.f, 0.f};
    float bC[4] = {0.f, 0.f, 0.f, 0.f};

    for (int it = 0; it < NITER; ++it) {
        // ---- stage converted tile (transposed, skewed) ----
#pragma unroll
        for (int h = 0; h < 2; ++h) {
            const int t = tl + h * 32;
#pragma unroll
            for (int j = 0; j < 4; ++j) {
                const int a = saddr(4 * cl4 + j, t);
                sd[a]  = ((const float*)&dd[h])[j];
                sev[a] = ((const float*)&ev[h])[j];
                se[a]  = ((const float*)&ee[h])[j];
            }
        }
        __syncthreads();   // sync1: staging complete; prior readers all done

        // Issue r load (used at store stage) and raw prefetch for next tile.
        float4 pr[2], pw[2], pk[2], pv[2];
#pragma unroll
        for (int h = 0; h < 2; ++h)
            pr[h] = __ldcs(&r[gco + (it * TTILE + tl + h * 32) * rowF4]);
        if (it + 1 < NITER) {
#pragma unroll
            for (int h = 0; h < 2; ++h) {
                const int g = gco + ((it + 1) * TTILE + tl + h * 32) * rowF4;
                pw[h] = __ldcs(&w[g]);  pk[h] = __ldcs(&k[g]);  pv[h] = __ldcs(&v[g]);
            }
        }

        // ---- per-warp serial-2 hybrid scan over 4 owned channels ----
#pragma unroll
        for (int sub = 0; sub < 4; ++sub) {
            const int ch = 4 * wid + sub;
            const int p  = saddr(ch, 2 * lane);          // even -> 8B aligned
            const float2 d2 = *(const float2*)&sd[p];
            const float2 e2 = *(const float2*)&se[p];
            const float2 x2 = *(const float2*)&sev[p];

            // lane-local composition of its 2 steps
            float D  = d2.x * d2.y;
            float A  = fmaf(x2.x, d2.y, x2.y);
            float Bv = fmaf(e2.x, d2.y, e2.y);

            // inclusive Kogge-Stone over lane aggregates
#pragma unroll
            for (int s = 1; s < 32; s <<= 1) {
                const float Dp = __shfl_up_sync(0xffffffffu, D, s);
                const float Ap = __shfl_up_sync(0xffffffffu, A, s);
                const float Bp = __shfl_up_sync(0xffffffffu, Bv, s);
                if (lane >= s) {
                    A  = fmaf(Ap, D, A);
                    Bv = fmaf(Bp, D, Bv);
                    D *= Dp;
                }
            }
            // exclusive prefix for this lane
            float Dx = __shfl_up_sync(0xffffffffu, D, 1);
            float Ax = __shfl_up_sync(0xffffffffu, A, 1);
            float Bx = __shfl_up_sync(0xffffffffu, Bv, 1);
            if (lane == 0) { Dx = 1.f; Ax = 0.f; Bx = 0.f; }
            const float Ain = fmaf(aC[sub], Dx, Ax);
            const float Bin = fmaf(bC[sub], Dx, Bx);

            // carry update from lane 31 inclusive aggregate
            const float D31 = __shfl_sync(0xffffffffu, D, 31);
            const float A31 = __shfl_sync(0xffffffffu, A, 31);
            const float B31 = __shfl_sync(0xffffffffu, Bv, 31);
            aC[sub] = fmaf(aC[sub], D31, A31);
            bC[sub] = fmaf(bC[sub], D31, B31);

            // replay the 2 local steps, emit a/(b+eps)
            const float a0 = fmaf(Ain, d2.x, x2.x);
            const float b0 = fmaf(Bin, d2.x, e2.x);
            const float a1 = fmaf(a0, d2.y, x2.y);
            const float b1 = fmaf(b0, d2.y, e2.y);
            *(float2*)&so[p] = make_float2(__fdividef(a0, b0 + WKV_EPS),
                                           __fdividef(a1, b1 + WKV_EPS));
        }
        __syncthreads();   // sync2: so complete; scan reads of sd/sev/se done

        // ---- readback + sigmoid(r) + coalesced store ----
#pragma unroll
        for (int h = 0; h < 2; ++h) {
            const int t = tl + h * 32;
            float4 o;
#pragma unroll
            for (int j = 0; j < 4; ++j)
                ((float*)&o)[j] = so[saddr(4 * cl4 + j, t)];
            const float4 rv = pr[h];
            o.x = __fdividef(o.x, 1.f + __expf(-rv.x));
            o.y = __fdividef(o.y, 1.f + __expf(-rv.y));
            o.z = __fdividef(o.z, 1.f + __expf(-rv.z));
            o.w = __fdividef(o.w, 1.f + __expf(-rv.w));
            __stcs(&out[gco + (it * TTILE + t) * rowF4], o);
        }

        // ---- convert prefetched raw tile for next iteration ----
        if (it + 1 < NITER) {
#pragma unroll
            for (int h = 0; h < 2; ++h)
                cvt(pw[h], pk[h], pv[h], dd[h], ee[h], ev[h]);
        }
    }
}

extern "C" void kernel_launch(void* const* d_in, const int* in_sizes, int n_in,
                              void* d_out, int out_size) {
    const float4* r = (const float4*)d_in[0];
    const float4* w = (const float4*)d_in[1];
    const float4* k = (const float4*)d_in[2];
    const float4* v = (const float4*)d_in[3];
    float4* o = (float4*)d_out;

    const int grid = B_ * (C_ / CBLK);    // 256 CTAs
    wkv_scan3<<<grid, THREADS, SMEMB>>>(r, w, k, v, o);
}

// round 10
// speedup vs baseline: 1.0102x; 1.0102x over previous
#include <cuda_runtime.h>

// RWKV WKV single-pass warp-scan, v4.
//   a_t = d_t a_{t-1} + ek_t v_t ; b_t = d_t b_{t-1} + ek_t
//   out = sigmoid(r) * a/(b+eps),  d = exp(-exp(w)), ek = exp(k)
//
// vs v2 (151.5us): CBLK 32->16 so grid doubles to 512 (one wave at 4 CTAs/SM,
// ~28 warps/SM resident vs 14), r dropped from the smem transpose (sigmoid
// applied at store from registers), no skew needed (banks distinct already).
// Keeps v2's double-buffered raw staging + full-tile-ahead register prefetch.

#define B_      8
#define T_      4096
#define C_      1024
#define CBLK    16
#define TTILE   64
#define NITER   (T_ / TTILE)      // 64
#define THREADS 256
#define SROW    66                // pad: bank = (2ch + t) mod 32, conflict-free
#define REGF    (CBLK * SROW)     // 1056 floats per region
#define SMEMB   (7 * REGF * 4)    // w,k,v x 2 bufs + so = 29568 B
#define WKV_EPS 1e-6f

__device__ __forceinline__ int saddr(int ch, int t) { return ch * SROW + t; }

__global__ void __launch_bounds__(THREADS, 4)
wkv_scan4(const float4* __restrict__ r, const float4* __restrict__ w,
          const float4* __restrict__ k, const float4* __restrict__ v,
          float4* __restrict__ out) {
    extern __shared__ float S[];
    float* so = S + 6 * REGF;     // output region (single buffer)

    const int tid  = threadIdx.x;
    const int lane = tid & 31;
    const int wid  = tid >> 5;    // warp owns channels 2*wid, 2*wid+1
    const int cl4  = tid & 3;     // float4 column (4 x 16B = 16 channels)
    const int tl   = tid >> 2;    // 0..63: one t-row per thread

    const int b  = blockIdx.x >> 6;               // 8 batches
    const int c0 = (blockIdx.x & 63) * CBLK;      // 64 channel blocks
    const int rowF4 = C_ / 4;                     // 256 float4 per time row
    const int gco   = (b * T_) * rowF4 + (c0 >> 2) + cl4;

    // Prefetch tile 0 (raw w,k,v; one float4 row per stream).
    float4 pw = __ldcs(&w[gco + tl * rowF4]);
    float4 pk = __ldcs(&k[gco + tl * rowF4]);
    float4 pv = __ldcs(&v[gco + tl * rowF4]);

    float aC[2] = {0.f, 0.f};
    float bC[2] = {0.f, 0.f};

    for (int it = 0; it < NITER; ++it) {
        const int bf = it & 1;
        float* sw = S + (0 * 2 + bf) * REGF;
        float* sk = S + (1 * 2 + bf) * REGF;
        float* sv = S + (2 * 2 + bf) * REGF;

        // ---- stage current tile (transposed; writer banks distinct) ----
#pragma unroll
        for (int j = 0; j < 4; ++j) {
            const int a = saddr(4 * cl4 + j, tl);
            sw[a] = ((const float*)&pw)[j];
            sk[a] = ((const float*)&pk)[j];
            sv[a] = ((const float*)&pv)[j];
        }

        // ---- prefetch: r for THIS tile (used at store), w/k/v for next ----
        float4 pr = __ldcs(&r[gco + (it * TTILE + tl) * rowF4]);
        if (it + 1 < NITER) {
            const int g = gco + ((it + 1) * TTILE + tl) * rowF4;
            pw = __ldcs(&w[g]);  pk = __ldcs(&k[g]);  pv = __ldcs(&v[g]);
        }
        __syncthreads();   // sync1: staging visible; prior so-readers done

        // ---- per-warp serial-2 hybrid scan over 2 owned channels ----
#pragma unroll
        for (int sub = 0; sub < 2; ++sub) {
            const int ch = 2 * wid + sub;
            const int p  = saddr(ch, 2 * lane);    // 8B-aligned LDS.64
            const float2 w2 = *(const float2*)&sw[p];
            const float2 k2 = *(const float2*)&sk[p];
            const float2 v2 = *(const float2*)&sv[p];

            const float d0  = __expf(-__expf(w2.x));
            const float d1  = __expf(-__expf(w2.y));
            const float e0  = __expf(k2.x);
            const float e1  = __expf(k2.y);
            const float ev0 = e0 * v2.x;
            const float ev1 = e1 * v2.y;

            // lane-local composition of its 2 steps
            float D  = d0 * d1;
            float A  = fmaf(ev0, d1, ev1);
            float Bv = fmaf(e0, d1, e1);

            // inclusive Kogge-Stone over lane aggregates
#pragma unroll
            for (int s = 1; s < 32; s <<= 1) {
                const float Dp = __shfl_up_sync(0xffffffffu, D, s);
                const float Ap = __shfl_up_sync(0xffffffffu, A, s);
                const float Bp = __shfl_up_sync(0xffffffffu, Bv, s);
                if (lane >= s) {
                    A  = fmaf(Ap, D, A);
                    Bv = fmaf(Bp, D, Bv);
                    D *= Dp;
                }
            }
            // exclusive prefix for this lane
            float Dx = __shfl_up_sync(0xffffffffu, D, 1);
            float Ax = __shfl_up_sync(0xffffffffu, A, 1);
            float Bx = __shfl_up_sync(0xffffffffu, Bv, 1);
            if (lane == 0) { Dx = 1.f; Ax = 0.f; Bx = 0.f; }
            const float Ain = fmaf(aC[sub], Dx, Ax);
            const float Bin = fmaf(bC[sub], Dx, Bx);

            // carry update from lane 31 inclusive aggregate
            const float D31 = __shfl_sync(0xffffffffu, D, 31);
            const float A31 = __shfl_sync(0xffffffffu, A, 31);
            const float B31 = __shfl_sync(0xffffffffu, Bv, 31);
            aC[sub] = fmaf(aC[sub], D31, A31);
            bC[sub] = fmaf(bC[sub], D31, B31);

            // replay the 2 local steps, emit a/(b+eps)
            const float a0 = fmaf(Ain, d0, ev0);
            const float b0 = fmaf(Bin, d0, e0);
            const float a1 = fmaf(a0, d1, ev1);
            const float b1 = fmaf(b0, d1, e1);
            *(float2*)&so[p] = make_float2(__fdividef(a0, b0 + WKV_EPS),
                                           __fdividef(a1, b1 + WKV_EPS));
        }
        __syncthreads();   // sync2: so complete; scan reads of this buf done

        // ---- readback + sigmoid(r) + coalesced float4 store ----
        float4 o;
#pragma unroll
        for (int j = 0; j < 4; ++j)
            ((float*)&o)[j] = so[saddr(4 * cl4 + j, tl)];
        o.x = __fdividef(o.x, 1.f + __expf(-pr.x));
        o.y = __fdividef(o.y, 1.f + __expf(-pr.y));
        o.z = __fdividef(o.z, 1.f + __expf(-pr.z));
        o.w = __fdividef(o.w, 1.f + __expf(-pr.w));
        __stcs(&out[gco + (it * TTILE + tl) * rowF4], o);
        // so is re-written only after the next iteration's sync1.
    }
}

extern "C" void kernel_launch(void* const* d_in, const int* in_sizes, int n_in,
                              void* d_out, int out_size) {
    const float4* r = (const float4*)d_in[0];
    const float4* w = (const float4*)d_in[1];
    const float4* k = (const float4*)d_in[2];
    const float4* v = (const float4*)d_in[3];
    float4* o = (float4*)d_out;

    const int grid = B_ * (C_ / CBLK);    // 512 CTAs
    wkv_scan4<<<grid, THREADS, SMEMB>>>(r, w, k, v, o);
}